// round 8
// baseline (speedup 1.0000x reference)
#include <cuda_runtime.h>

#define N197   197
#define NN     38809        // 197*197
#define NNP    38812        // padded stride (float4-aligned)
#define NBATCH 32
#define NLAY   2            // processed layers: 4 and 11
#define KDISC  9702         // int(197*197*0.25)
#define PADR   256
#define PADC   208
#define NTF    1024

__device__ float    g_attn[NLAY * NBATCH * NNP];
__device__ float    g_norm[NLAY * NBATCH * PADR * PADC];
__device__ unsigned g_hist[NLAY * NBATCH * 4096];   // zero-init; fused re-zeroes after use

// ---------------------------------------------------------------------------
// 1) mean over heads + round-0 histogram (top 12 float bits) under DRAM shadow
//    (exact R6 form — measured 24.0us @ 65% DRAM)
// ---------------------------------------------------------------------------
__global__ void __launch_bounds__(256) mean_kernel(const float* __restrict__ in) {
    __shared__ unsigned hist[4096];
    for (int i = threadIdx.x; i < 4096; i += 256) hist[i] = 0u;
    __syncthreads();

    int lb = blockIdx.y;                 // 0..63 = li*32 + b
    int li = lb >> 5, b = lb & 31;
    int layer = li ? 11 : 4;
    const float* __restrict__ base = in + ((long)(layer * NBATCH + b) * 12) * NN;
    float* dst = g_attn + (long)lb * NNP;
    const int lane   = threadIdx.x & 31;
    const int stride = gridDim.x * 256;
    const int ITER   = (NN + stride - 1) / stride;

    for (int k = 0; k < ITER; k++) {
        int p = k * stride + blockIdx.x * 256 + threadIdx.x;
        bool valid = p < NN;
        float s = 0.f;
        if (valid) {
#pragma unroll
            for (int h = 0; h < 12; h++) s += __ldg(&base[(long)h * NN + p]);
            s *= (1.0f / 12.0f);
            dst[p] = s;
        }
        unsigned key = __float_as_uint(s) >> 20;
        unsigned m = __ballot_sync(0xffffffffu, valid);
        if (valid) {
            unsigned grp = __match_any_sync(m, key);
            if (lane == (int)__ffs(grp) - 1) atomicAdd(&hist[key], __popc(grp));
        }
    }
    __syncthreads();
    for (int i = threadIdx.x; i < 4096; i += 256) {
        unsigned c = hist[i];
        if (c) atomicAdd(&g_hist[lb * 4096 + i], c);
    }
}

// ---------------------------------------------------------------------------
// block-wide "pick the bucket containing rank"
// s_out: [0]=chosen bucket, [1]=rank within bucket, [2]=count below
// ---------------------------------------------------------------------------
template<int PER>
__device__ __forceinline__ void block_pick(const unsigned* cnts, int nb, int rank,
                                           unsigned* wtot, int* s_out) {
    const int t = threadIdx.x, lane = t & 31, wid = t >> 5;
    const int base = t * PER;
    unsigned h[PER];
    unsigned sum = 0;
    if (base < nb) {
#pragma unroll
        for (int j = 0; j < PER; j++) { h[j] = cnts[base + j]; sum += h[j]; }
    }
    unsigned x = sum;
#pragma unroll
    for (int o = 1; o < 32; o <<= 1) {
        unsigned y = __shfl_up_sync(0xffffffffu, x, o);
        if (lane >= o) x += y;
    }
    if (lane == 31) wtot[wid] = x;
    __syncthreads();
    if (wid == 0) {
        unsigned y = wtot[lane];
#pragma unroll
        for (int o = 1; o < 32; o <<= 1) {
            unsigned z = __shfl_up_sync(0xffffffffu, y, o);
            if (lane >= o) y += z;
        }
        wtot[lane] = y;
    }
    __syncthreads();
    unsigned excl = x - sum + (wid ? wtot[wid - 1] : 0u);
    if (base < nb && (unsigned)rank >= excl && (unsigned)rank < excl + sum) {
        unsigned c = excl; int ch = base;
#pragma unroll
        for (int j = 0; j < PER; j++) {
            if (c + h[j] > (unsigned)rank) { ch = base + j; break; }
            c += h[j];
        }
        s_out[0] = ch; s_out[1] = rank - (int)c; s_out[2] = (int)c;
    }
    __syncthreads();
}

// ---------------------------------------------------------------------------
// 2) fused: pick0 -> load(L2)+hist1 -> pick1 -> [rare round-2/ties]
//    -> discard+rowsum -> normalized padded write     (also re-zeroes g_hist)
// ---------------------------------------------------------------------------
__global__ void __launch_bounds__(NTF) fused_kernel() {
    extern __shared__ float sm[];          // NN floats
    __shared__ unsigned hist[4096];
    __shared__ unsigned wtot[32];
    __shared__ int s_pick[3];
    __shared__ float rowden[N197];

    const int lb = blockIdx.x;
    const int t = threadIdx.x, lane = t & 31, wid = t >> 5;

    // ---- round 0 pick from global histogram ----
    block_pick<4>(&g_hist[lb * 4096], 4096, KDISC - 1, wtot, s_pick);
    const int B1 = s_pick[0];
    int rank = s_pick[1];

    // zero smem hist AND re-zero our g_hist slice (graph-replay invariant)
    for (int i = t; i < 4096; i += NTF) { hist[i] = 0u; g_hist[lb * 4096 + i] = 0u; }
    __syncthreads();

    // ---- load matrix to smem + round-1 hist (plain atomics; sparse hits) ----
    const float* src = g_attn + (long)lb * NNP;
    const float4* s4 = (const float4*)src;
    float4* d4 = (float4*)sm;
    const int N4 = NN / 4;                 // 9702
    const int IT4 = (N4 + NTF - 1) / NTF;  // 10
    for (int k = 0; k < IT4; k++) {
        int i = k * NTF + t;
        if (i < N4) {
            float4 a = s4[i];
            d4[i] = a;
            const float vv[4] = {a.x, a.y, a.z, a.w};
#pragma unroll
            for (int j = 0; j < 4; j++) {
                unsigned key = __float_as_uint(vv[j]);
                if ((int)(key >> 20) == B1) atomicAdd(&hist[(key >> 8) & 0xFFFu], 1u);
            }
        }
    }
    if (t == 0) {                          // tail element 38808
        float v = src[NN - 1]; sm[NN - 1] = v;
        unsigned key = __float_as_uint(v);
        if ((int)(key >> 20) == B1) atomicAdd(&hist[(key >> 8) & 0xFFFu], 1u);
    }
    __syncthreads();

    block_pick<4>(hist, 4096, rank, wtot, s_pick);
    const int B2 = s_pick[0];
    rank = s_pick[1];
    const unsigned K24 = ((unsigned)B1 << 12) | (unsigned)B2;
    const unsigned ties2 = hist[B2];

    int mode;           // 0: zero key24<=K24 | 1: zero key<=T | 2: zero key<T (ties pre-zeroed)
    unsigned T = 0;
    if (ties2 == 1u) {
        mode = 0;       // unique kth element at 24-bit granularity
    } else {
        // ---- round 2: low 8 bits among key24==K24 ----
        for (int i = t; i < 256; i += NTF) hist[i] = 0u;
        __syncthreads();
        const int IT = (NN + NTF - 1) / NTF;   // 38
        for (int k = 0; k < IT; k++) {
            int i = k * NTF + t;
            if (i < NN) {
                unsigned key = __float_as_uint(sm[i]);
                if ((key >> 8) == K24) atomicAdd(&hist[key & 0xFFu], 1u);
            }
        }
        __syncthreads();
        block_pick<1>(hist, 256, rank, wtot, s_pick);
        const int B3 = s_pick[0];
        const int rank3 = s_pick[1];
        T = (K24 << 8) | (unsigned)B3;
        const unsigned ties3 = hist[B3];
        const int need = rank3 + 1;            // #(==T) among the k smallest
        if ((unsigned)need == ties3) {
            mode = 1;
        } else {
            mode = 2;
            const int SEG = (NN + NTF - 1) / NTF;
            int start = t * SEG, end = min(start + SEG, NN);
            int cnt = 0;
            for (int i = start; i < end; i++)
                if (__float_as_uint(sm[i]) == T) cnt++;
            int x = cnt;
#pragma unroll
            for (int o = 1; o < 32; o <<= 1) {
                int y = __shfl_up_sync(0xffffffffu, x, o);
                if (lane >= o) x += y;
            }
            if (lane == 31) wtot[wid] = (unsigned)x;
            __syncthreads();
            if (wid == 0) {
                unsigned y = wtot[lane];
#pragma unroll
                for (int o = 1; o < 32; o <<= 1) {
                    unsigned z = __shfl_up_sync(0xffffffffu, y, o);
                    if (lane >= o) y += z;
                }
                wtot[lane] = y;
            }
            __syncthreads();
            int pre = x - cnt + (wid ? (int)wtot[wid - 1] : 0);
            for (int i = start; i < end; i++) {
                if (__float_as_uint(sm[i]) == T) {
                    if (pre < need && i != 0) sm[i] = 0.f;
                    pre++;
                }
            }
            __syncthreads();
        }
    }

    // ---- discard + row sums in one pass (warp per row) ----
    for (int r = wid; r < N197; r += 32) {
        float s = 0.f;
        const int rowbase = r * N197;
        for (int c = lane; c < N197; c += 32) {
            int i = rowbase + c;
            float v = sm[i];
            unsigned key = __float_as_uint(v);
            bool z = (mode == 0) ? ((key >> 8) <= K24)
                   : (mode == 1) ? (key <= T)
                                 : (key < T);
            if (z && i != 0) { sm[i] = 0.f; v = 0.f; }
            s += v;
        }
#pragma unroll
        for (int o = 16; o; o >>= 1) s += __shfl_xor_sync(0xffffffffu, s, o);
        if (lane == 0) rowden[r] = s + 1.0f;    // the *0.5 cancels: (x+d)/(sum+1)
    }
    __syncthreads();

    // ---- normalized float4 write into zero-padded 256x208 buffer ----
    float4* o4 = (float4*)(g_norm + (long)lb * (PADR * PADC));
    const int NV = PADR * PADC / 4;            // 13312
    const int C4 = PADC / 4;                   // 52
    for (int i = t; i < NV; i += NTF) {
        int r = i / C4;
        int c = (i - r * C4) * 4;
        float4 val = make_float4(0.f, 0.f, 0.f, 0.f);
        if (r < N197) {
            float inv = 1.0f / rowden[r];
            float* e = &val.x;
#pragma unroll
            for (int j = 0; j < 4; j++) {
                int cc = c + j;
                if (cc < N197) e[j] = (sm[r * N197 + cc] + (r == cc ? 1.f : 0.f)) * inv;
            }
        }
        o4[i] = val;
    }
}

// ---------------------------------------------------------------------------
// 3) out[b] = A11[b] @ A4[b]: 64x64 tile, MOV-free f32x2 inner loop,
//    pre-splatted B pairs in smem, double-buffered (one sync per k-tile)
// ---------------------------------------------------------------------------
#define BM 64
#define BN 64
#define BK 16
#define ASTR 68     // As row stride in floats (16B multiple)

#define FMAF2(d, a, bb) \
    asm("fma.rn.f32x2 %0, %1, %2, %0;" : "+l"(d) : "l"(a), "l"(bb))

__global__ void __launch_bounds__(256) gemm_kernel(float* __restrict__ C) {
    const int b = blockIdx.z;
    const float* __restrict__ A  = g_norm + (long)(NBATCH + b) * (PADR * PADC); // layer 11
    const float* __restrict__ Bm = g_norm + (long)b * (PADR * PADC);            // layer 4
    C += (long)b * NN;

    __shared__ float              As[2][BK][ASTR];         // transposed: As[k][m]
    __shared__ unsigned long long Bs2[2][BK][BN];          // splatted (v,v) pairs

    const int t  = threadIdx.x;        // 0..255
    const int tx = t & 15;             // n-group: 4 cols
    const int ty = t >> 4;             // m-group: 4 rows (2 pairs)
    const int row0 = blockIdx.y * BM, col0 = blockIdx.x * BN;

    const int ar = t >> 2, aq = t & 3;     // As loader: row ar, k-quad aq
    const int bk = t >> 4, bq = t & 15;    // Bs loader: k-row bk, col-quad bq

    unsigned long long acc[2][4];
#pragma unroll
    for (int mp = 0; mp < 2; mp++)
#pragma unroll
        for (int n = 0; n < 4; n++) acc[mp][n] = 0ull;

    // prefetch + store tile 0
    float4 pa = *(const float4*)&A[(row0 + ar) * PADC + aq * 4];
    float4 pb = *(const float4*)&Bm[bk * PADC + col0 + bq * 4];
    {
        As[0][aq * 4 + 0][ar] = pa.x;
        As[0][aq * 4 + 1][ar] = pa.y;
        As[0][aq * 4 + 2][ar] = pa.z;
        As[0][aq * 4 + 3][ar] = pa.w;
        const float bv[4] = {pb.x, pb.y, pb.z, pb.w};
#pragma unroll
        for (int j = 0; j < 4; j++) {
            unsigned long long s;
            asm("mov.b64 %0, {%1, %1};" : "=l"(s) : "r"(__float_as_uint(bv[j])));
            Bs2[0][bk][bq * 4 + j] = s;
        }
    }
    __syncthreads();

    const int NKT = PADC / BK;             // 13
    for (int kt = 0; kt < NKT; kt++) {
        const int buf = kt & 1;
        if (kt + 1 < NKT) {                // global prefetch of next tile
            int k0 = (kt + 1) * BK;
            pa = *(const float4*)&A[(row0 + ar) * PADC + k0 + aq * 4];
            pb = *(const float4*)&Bm[(k0 + bk) * PADC + col0 + bq * 4];
        }

#pragma unroll
        for (int kk = 0; kk < BK; kk++) {
            ulonglong2 a01 = *(const ulonglong2*)&As[buf][kk][ty * 4];
            ulonglong2 b01 = *(const ulonglong2*)&Bs2[buf][kk][tx * 4];
            ulonglong2 b23 = *(const ulonglong2*)&Bs2[buf][kk][tx * 4 + 2];
            FMAF2(acc[0][0], a01.x, b01.x);
            FMAF2(acc[1][0], a01.y, b01.x);
            FMAF2(acc[0][1], a01.x, b01.y);
            FMAF2(acc[1][1], a01.y, b01.y);
            FMAF2(acc[0][2], a01.x, b23.x);
            FMAF2(acc[1][2], a01.y, b23.x);
            FMAF2(acc[0][3], a01.x, b23.y);
            FMAF2(acc[1][3], a01.y, b23.y);
        }

        if (kt + 1 < NKT) {                // store next tile into the other buffer
            const int nb = buf ^ 1;
            As[nb][aq * 4 + 0][ar] = pa.x;
            As[nb][aq * 4 + 1][ar] = pa.y;
            As[nb][aq * 4 + 2][ar] = pa.z;
            As[nb][aq * 4 + 3][ar] = pa.w;
            const float bv[4] = {pb.x, pb.y, pb.z, pb.w};
#pragma unroll
            for (int j = 0; j < 4; j++) {
                unsigned long long s;
                asm("mov.b64 %0, {%1, %1};" : "=l"(s) : "r"(__float_as_uint(bv[j])));
                Bs2[nb][bk][bq * 4 + j] = s;
            }
            __syncthreads();
        }
    }

#pragma unroll
    for (int mp = 0; mp < 2; mp++) {
#pragma unroll
        for (int n = 0; n < 4; n++) {
            unsigned ulo, uhi;
            asm("mov.b64 {%0, %1}, %2;" : "=r"(ulo), "=r"(uhi) : "l"(acc[mp][n]));
            int gr = row0 + ty * 4 + mp * 2;
            int gc = col0 + tx * 4 + n;
            if (gc < N197) {
                if (gr < N197)     C[gr * N197 + gc]       = __uint_as_float(ulo);
                if (gr + 1 < N197) C[(gr + 1) * N197 + gc] = __uint_as_float(uhi);
            }
        }
    }
}

// ---------------------------------------------------------------------------
extern "C" void kernel_launch(void* const* d_in, const int* in_sizes, int n_in,
                              void* d_out, int out_size) {
    const float* attn = (const float*)d_in[0];  // (12,32,12,197,197) fp32
    float* out = (float*)d_out;                 // (32,197,197) fp32
    (void)in_sizes; (void)n_in; (void)out_size;

    cudaFuncSetAttribute(fused_kernel, cudaFuncAttributeMaxDynamicSharedMemorySize,
                         NN * (int)sizeof(float));

    dim3 gm(40, NLAY * NBATCH);
    mean_kernel<<<gm, 256>>>(attn);
    fused_kernel<<<NLAY * NBATCH, NTF, NN * sizeof(float)>>>();
    dim3 gg((N197 + BN - 1) / BN, (N197 + BM - 1) / BM, NBATCH);
    gemm_kernel<<<gg, 256>>>(out);
}

// round 9
// speedup vs baseline: 1.5490x; 1.5490x over previous
#include <cuda_runtime.h>

#define N197   197
#define NN     38809        // 197*197
#define NNP    38812        // padded stride (float4-aligned)
#define NBATCH 32
#define NLAY   2            // processed layers: 4 and 11
#define KDISC  9702         // int(197*197*0.25)
#define PADR   256
#define PADC   208
#define NTF    1024

__device__ float    g_attn[NLAY * NBATCH * NNP];
__device__ float    g_norm[NLAY * NBATCH * PADR * PADC];
__device__ unsigned g_hist[NLAY * NBATCH * 4096];   // zero-init; fused re-zeroes after use

// ---------------------------------------------------------------------------
// 1) mean over heads + round-0 histogram (top 12 float bits) under DRAM shadow
//    (exact R6 form — measured 24.0us @ 65% DRAM)
// ---------------------------------------------------------------------------
__global__ void __launch_bounds__(256) mean_kernel(const float* __restrict__ in) {
    __shared__ unsigned hist[4096];
    for (int i = threadIdx.x; i < 4096; i += 256) hist[i] = 0u;
    __syncthreads();

    int lb = blockIdx.y;                 // 0..63 = li*32 + b
    int li = lb >> 5, b = lb & 31;
    int layer = li ? 11 : 4;
    const float* __restrict__ base = in + ((long)(layer * NBATCH + b) * 12) * NN;
    float* dst = g_attn + (long)lb * NNP;
    const int lane   = threadIdx.x & 31;
    const int stride = gridDim.x * 256;
    const int ITER   = (NN + stride - 1) / stride;

    for (int k = 0; k < ITER; k++) {
        int p = k * stride + blockIdx.x * 256 + threadIdx.x;
        bool valid = p < NN;
        float s = 0.f;
        if (valid) {
#pragma unroll
            for (int h = 0; h < 12; h++) s += __ldg(&base[(long)h * NN + p]);
            s *= (1.0f / 12.0f);
            dst[p] = s;
        }
        unsigned key = __float_as_uint(s) >> 20;
        unsigned m = __ballot_sync(0xffffffffu, valid);
        if (valid) {
            unsigned grp = __match_any_sync(m, key);
            if (lane == (int)__ffs(grp) - 1) atomicAdd(&hist[key], __popc(grp));
        }
    }
    __syncthreads();
    for (int i = threadIdx.x; i < 4096; i += 256) {
        unsigned c = hist[i];
        if (c) atomicAdd(&g_hist[lb * 4096 + i], c);
    }
}

// ---------------------------------------------------------------------------
// block-wide "pick the bucket containing rank"
// ---------------------------------------------------------------------------
template<int PER>
__device__ __forceinline__ void block_pick(const unsigned* cnts, int nb, int rank,
                                           unsigned* wtot, int* s_out) {
    const int t = threadIdx.x, lane = t & 31, wid = t >> 5;
    const int base = t * PER;
    unsigned h[PER];
    unsigned sum = 0;
    if (base < nb) {
#pragma unroll
        for (int j = 0; j < PER; j++) { h[j] = cnts[base + j]; sum += h[j]; }
    }
    unsigned x = sum;
#pragma unroll
    for (int o = 1; o < 32; o <<= 1) {
        unsigned y = __shfl_up_sync(0xffffffffu, x, o);
        if (lane >= o) x += y;
    }
    if (lane == 31) wtot[wid] = x;
    __syncthreads();
    if (wid == 0) {
        unsigned y = wtot[lane];
#pragma unroll
        for (int o = 1; o < 32; o <<= 1) {
            unsigned z = __shfl_up_sync(0xffffffffu, y, o);
            if (lane >= o) y += z;
        }
        wtot[lane] = y;
    }
    __syncthreads();
    unsigned excl = x - sum + (wid ? wtot[wid - 1] : 0u);
    if (base < nb && (unsigned)rank >= excl && (unsigned)rank < excl + sum) {
        unsigned c = excl; int ch = base;
#pragma unroll
        for (int j = 0; j < PER; j++) {
            if (c + h[j] > (unsigned)rank) { ch = base + j; break; }
            c += h[j];
        }
        s_out[0] = ch; s_out[1] = rank - (int)c; s_out[2] = (int)c;
    }
    __syncthreads();
}

// ---------------------------------------------------------------------------
// 2) fused: pick0 -> load(L2)+hist1 -> pick1 -> [rare round-2/ties]
//    -> discard+rowsum -> normalized padded write     (also re-zeroes g_hist)
// ---------------------------------------------------------------------------
__global__ void __launch_bounds__(NTF) fused_kernel() {
    extern __shared__ float sm[];          // NN floats
    __shared__ unsigned hist[4096];
    __shared__ unsigned wtot[32];
    __shared__ int s_pick[3];
    __shared__ float rowden[N197];

    const int lb = blockIdx.x;
    const int t = threadIdx.x, lane = t & 31, wid = t >> 5;

    block_pick<4>(&g_hist[lb * 4096], 4096, KDISC - 1, wtot, s_pick);
    const int B1 = s_pick[0];
    int rank = s_pick[1];

    for (int i = t; i < 4096; i += NTF) { hist[i] = 0u; g_hist[lb * 4096 + i] = 0u; }
    __syncthreads();

    const float* src = g_attn + (long)lb * NNP;
    const float4* s4 = (const float4*)src;
    float4* d4 = (float4*)sm;
    const int N4 = NN / 4;                 // 9702
    const int IT4 = (N4 + NTF - 1) / NTF;  // 10
    for (int k = 0; k < IT4; k++) {
        int i = k * NTF + t;
        if (i < N4) {
            float4 a = s4[i];
            d4[i] = a;
            const float vv[4] = {a.x, a.y, a.z, a.w};
#pragma unroll
            for (int j = 0; j < 4; j++) {
                unsigned key = __float_as_uint(vv[j]);
                if ((int)(key >> 20) == B1) atomicAdd(&hist[(key >> 8) & 0xFFFu], 1u);
            }
        }
    }
    if (t == 0) {                          // tail element 38808
        float v = src[NN - 1]; sm[NN - 1] = v;
        unsigned key = __float_as_uint(v);
        if ((int)(key >> 20) == B1) atomicAdd(&hist[(key >> 8) & 0xFFFu], 1u);
    }
    __syncthreads();

    block_pick<4>(hist, 4096, rank, wtot, s_pick);
    const int B2 = s_pick[0];
    rank = s_pick[1];
    const unsigned K24 = ((unsigned)B1 << 12) | (unsigned)B2;
    const unsigned ties2 = hist[B2];

    int mode;           // 0: zero key24<=K24 | 1: zero key<=T | 2: zero key<T (ties pre-zeroed)
    unsigned T = 0;
    if (ties2 == 1u) {
        mode = 0;
    } else {
        for (int i = t; i < 256; i += NTF) hist[i] = 0u;
        __syncthreads();
        const int IT = (NN + NTF - 1) / NTF;   // 38
        for (int k = 0; k < IT; k++) {
            int i = k * NTF + t;
            if (i < NN) {
                unsigned key = __float_as_uint(sm[i]);
                if ((key >> 8) == K24) atomicAdd(&hist[key & 0xFFu], 1u);
            }
        }
        __syncthreads();
        block_pick<1>(hist, 256, rank, wtot, s_pick);
        const int B3 = s_pick[0];
        const int rank3 = s_pick[1];
        T = (K24 << 8) | (unsigned)B3;
        const unsigned ties3 = hist[B3];
        const int need = rank3 + 1;
        if ((unsigned)need == ties3) {
            mode = 1;
        } else {
            mode = 2;
            const int SEG = (NN + NTF - 1) / NTF;
            int start = t * SEG, end = min(start + SEG, NN);
            int cnt = 0;
            for (int i = start; i < end; i++)
                if (__float_as_uint(sm[i]) == T) cnt++;
            int x = cnt;
#pragma unroll
            for (int o = 1; o < 32; o <<= 1) {
                int y = __shfl_up_sync(0xffffffffu, x, o);
                if (lane >= o) x += y;
            }
            if (lane == 31) wtot[wid] = (unsigned)x;
            __syncthreads();
            if (wid == 0) {
                unsigned y = wtot[lane];
#pragma unroll
                for (int o = 1; o < 32; o <<= 1) {
                    unsigned z = __shfl_up_sync(0xffffffffu, y, o);
                    if (lane >= o) y += z;
                }
                wtot[lane] = y;
            }
            __syncthreads();
            int pre = x - cnt + (wid ? (int)wtot[wid - 1] : 0);
            for (int i = start; i < end; i++) {
                if (__float_as_uint(sm[i]) == T) {
                    if (pre < need && i != 0) sm[i] = 0.f;
                    pre++;
                }
            }
            __syncthreads();
        }
    }

    // ---- discard + row sums in one pass (warp per row) ----
    for (int r = wid; r < N197; r += 32) {
        float s = 0.f;
        const int rowbase = r * N197;
        for (int c = lane; c < N197; c += 32) {
            int i = rowbase + c;
            float v = sm[i];
            unsigned key = __float_as_uint(v);
            bool z = (mode == 0) ? ((key >> 8) <= K24)
                   : (mode == 1) ? (key <= T)
                                 : (key < T);
            if (z && i != 0) { sm[i] = 0.f; v = 0.f; }
            s += v;
        }
#pragma unroll
        for (int o = 16; o; o >>= 1) s += __shfl_xor_sync(0xffffffffu, s, o);
        if (lane == 0) rowden[r] = s + 1.0f;    // the *0.5 cancels: (x+d)/(sum+1)
    }
    __syncthreads();

    // ---- normalized float4 write into zero-padded 256x208 buffer ----
    float4* o4 = (float4*)(g_norm + (long)lb * (PADR * PADC));
    const int NV = PADR * PADC / 4;            // 13312
    const int C4 = PADC / 4;                   // 52
    for (int i = t; i < NV; i += NTF) {
        int r = i / C4;
        int c = (i - r * C4) * 4;
        float4 val = make_float4(0.f, 0.f, 0.f, 0.f);
        if (r < N197) {
            float inv = 1.0f / rowden[r];
            float* e = &val.x;
#pragma unroll
            for (int j = 0; j < 4; j++) {
                int cc = c + j;
                if (cc < N197) e[j] = (sm[r * N197 + cc] + (r == cc ? 1.f : 0.f)) * inv;
            }
        }
        o4[i] = val;
    }
}

// ---------------------------------------------------------------------------
// 3) out[b] = A11[b] @ A4[b]: 128x128 tile, 256 threads, 8x8 microtile,
//    m-paired f32x2 (A pairs native from LDS), conflict-free padded B groups.
// ---------------------------------------------------------------------------
#define BM 128
#define BN 128
#define BK 16
#define ASTR 132        // As row stride in floats (16B multiple)
#define BROW 192        // Bs row: 16 groups * 12 floats (8 data + 4 pad)

#define FMAF2(d, a, bb) \
    asm("fma.rn.f32x2 %0, %1, %2, %0;" : "+l"(d) : "l"(a), "l"(bb))
#define SPLAT2(d, v) \
    asm("mov.b64 %0, {%1, %1};" : "=l"(d) : "r"(__float_as_uint(v)))

__global__ void __launch_bounds__(256) gemm_kernel(float* __restrict__ C) {
    const int b = blockIdx.z;
    const float* __restrict__ A  = g_norm + (long)(NBATCH + b) * (PADR * PADC); // layer 11
    const float* __restrict__ Bm = g_norm + (long)b * (PADR * PADC);            // layer 4
    C += (long)b * NN;

    __shared__ float As[BK][ASTR];     // transposed: As[k][m]  (8.4 KB)
    __shared__ float Bs[BK * BROW];    // padded groups         (12.3 KB)

    const int t  = threadIdx.x;        // 0..255
    const int tx = t & 15;             // n-group: 8 cols (col0 + tx*8)
    const int ty = t >> 4;             // m-group: 8 rows (row0 + ty*8)
    const int row0 = blockIdx.y * BM, col0 = blockIdx.x * BN;

    unsigned long long acc[4][8];      // [m-pair][n]
#pragma unroll
    for (int mp = 0; mp < 4; mp++)
#pragma unroll
        for (int n = 0; n < 8; n++) acc[mp][n] = 0ull;

    // loader indices: 512 float4 per tile for each of A and B; 2 per thread
    float4 pa[2], pb[2];
#pragma unroll
    for (int l = 0; l < 2; l++) {
        int idx = t + l * 256;
        int aq = idx >> 7, ar = idx & 127;              // A: k-quad, row
        pa[l] = *(const float4*)&A[(row0 + ar) * PADC + aq * 4];
        int bk = idx >> 5, cq = idx & 31;               // B: k-row, col-quad
        pb[l] = *(const float4*)&Bm[bk * PADC + col0 + cq * 4];
    }

    const int NKT = PADC / BK;             // 13
    for (int kt = 0; kt < NKT; kt++) {
        // store tile from prefetch regs
#pragma unroll
        for (int l = 0; l < 2; l++) {
            int idx = t + l * 256;
            int aq = idx >> 7, ar = idx & 127;
            As[aq * 4 + 0][ar] = pa[l].x;
            As[aq * 4 + 1][ar] = pa[l].y;
            As[aq * 4 + 2][ar] = pa[l].z;
            As[aq * 4 + 3][ar] = pa[l].w;
            int bk = idx >> 5, cq = idx & 31;
            int g = cq >> 1, w = cq & 1;
            *(float4*)&Bs[bk * BROW + g * 12 + w * 4] = pb[l];
        }
        __syncthreads();

        // prefetch next tile
        if (kt + 1 < NKT) {
            int k0 = (kt + 1) * BK;
#pragma unroll
            for (int l = 0; l < 2; l++) {
                int idx = t + l * 256;
                int aq = idx >> 7, ar = idx & 127;
                pa[l] = *(const float4*)&A[(row0 + ar) * PADC + k0 + aq * 4];
                int bk = idx >> 5, cq = idx & 31;
                pb[l] = *(const float4*)&Bm[(k0 + bk) * PADC + col0 + cq * 4];
            }
        }

#pragma unroll
        for (int kk = 0; kk < BK; kk++) {
            ulonglong2 a01 = *(const ulonglong2*)&As[kk][ty * 8];      // m-pairs 0,1
            ulonglong2 a23 = *(const ulonglong2*)&As[kk][ty * 8 + 4];  // m-pairs 2,3
            const float* bg = &Bs[kk * BROW + tx * 12];
            float4 b0 = *(const float4*)bg;
            {
                unsigned long long s0, s1, s2, s3;
                SPLAT2(s0, b0.x); SPLAT2(s1, b0.y); SPLAT2(s2, b0.z); SPLAT2(s3, b0.w);
                FMAF2(acc[0][0], a01.x, s0); FMAF2(acc[1][0], a01.y, s0);
                FMAF2(acc[2][0], a23.x, s0); FMAF2(acc[3][0], a23.y, s0);
                FMAF2(acc[0][1], a01.x, s1); FMAF2(acc[1][1], a01.y, s1);
                FMAF2(acc[2][1], a23.x, s1); FMAF2(acc[3][1], a23.y, s1);
                FMAF2(acc[0][2], a01.x, s2); FMAF2(acc[1][2], a01.y, s2);
                FMAF2(acc[2][2], a23.x, s2); FMAF2(acc[3][2], a23.y, s2);
                FMAF2(acc[0][3], a01.x, s3); FMAF2(acc[1][3], a01.y, s3);
                FMAF2(acc[2][3], a23.x, s3); FMAF2(acc[3][3], a23.y, s3);
            }
            float4 b1 = *(const float4*)(bg + 4);
            {
                unsigned long long s0, s1, s2, s3;
                SPLAT2(s0, b1.x); SPLAT2(s1, b1.y); SPLAT2(s2, b1.z); SPLAT2(s3, b1.w);
                FMAF2(acc[0][4], a01.x, s0); FMAF2(acc[1][4], a01.y, s0);
                FMAF2(acc[2][4], a23.x, s0); FMAF2(acc[3][4], a23.y, s0);
                FMAF2(acc[0][5], a01.x, s1); FMAF2(acc[1][5], a01.y, s1);
                FMAF2(acc[2][5], a23.x, s1); FMAF2(acc[3][5], a23.y, s1);
                FMAF2(acc[0][6], a01.x, s2); FMAF2(acc[1][6], a01.y, s2);
                FMAF2(acc[2][6], a23.x, s2); FMAF2(acc[3][6], a23.y, s2);
                FMAF2(acc[0][7], a01.x, s3); FMAF2(acc[1][7], a01.y, s3);
                FMAF2(acc[2][7], a23.x, s3); FMAF2(acc[3][7], a23.y, s3);
            }
        }
        __syncthreads();
    }

#pragma unroll
    for (int mp = 0; mp < 4; mp++) {
#pragma unroll
        for (int n = 0; n < 8; n++) {
            unsigned ulo, uhi;
            asm("mov.b64 {%0, %1}, %2;" : "=r"(ulo), "=r"(uhi) : "l"(acc[mp][n]));
            int gr = row0 + ty * 8 + mp * 2;
            int gc = col0 + tx * 8 + n;
            if (gc < N197) {
                if (gr < N197)     C[gr * N197 + gc]       = __uint_as_float(ulo);
                if (gr + 1 < N197) C[(gr + 1) * N197 + gc] = __uint_as_float(uhi);
            }
        }
    }
}

// ---------------------------------------------------------------------------
extern "C" void kernel_launch(void* const* d_in, const int* in_sizes, int n_in,
                              void* d_out, int out_size) {
    const float* attn = (const float*)d_in[0];  // (12,32,12,197,197) fp32
    float* out = (float*)d_out;                 // (32,197,197) fp32
    (void)in_sizes; (void)n_in; (void)out_size;

    cudaFuncSetAttribute(fused_kernel, cudaFuncAttributeMaxDynamicSharedMemorySize,
                         NN * (int)sizeof(float));

    dim3 gm(40, NLAY * NBATCH);
    mean_kernel<<<gm, 256>>>(attn);
    fused_kernel<<<NLAY * NBATCH, NTF, NN * sizeof(float)>>>();
    dim3 gg((N197 + BN - 1) / BN, (N197 + BM - 1) / BM, NBATCH);
    gemm_kernel<<<gg, 256>>>(out);
}